// round 3
// baseline (speedup 1.0000x reference)
#include <cuda_runtime.h>
#include <cstdint>

// Problem constants (fixed instance)
constexpr int S   = 16;
constexpr int EXT = 64;
constexpr int SE  = S * EXT;          // 1024
constexpr int NN  = 8192;             // nodes
constexpr int EE  = 16384;            // edges
constexpr int PP  = 2048;             // paths

// Dense coefficient tensor, duplicated into float2 {c,c} so LDS.128 yields two
// ready f32x2 operands. Layout: idx = (i*16 + j)*16 + k   (k contiguous)
__device__ __align__(16) float2 g_C2[S * S * S];

// ---------------- f32x2 packed helpers (sm_103a) ----------------
__device__ __forceinline__ unsigned long long f32x2_pack(float lo, float hi) {
    unsigned long long d;
    asm("mov.b64 %0, {%1, %2};" : "=l"(d) : "f"(lo), "f"(hi));
    return d;
}
__device__ __forceinline__ void f32x2_unpack(unsigned long long v, float& lo, float& hi) {
    asm("mov.b64 {%0, %1}, %2;" : "=f"(lo), "=f"(hi) : "l"(v));
}
__device__ __forceinline__ unsigned long long f32x2_mul(unsigned long long a, unsigned long long b) {
    unsigned long long d;
    asm("mul.rn.f32x2 %0, %1, %2;" : "=l"(d) : "l"(a), "l"(b));
    return d;
}
__device__ __forceinline__ unsigned long long f32x2_fma(unsigned long long a, unsigned long long b,
                                                        unsigned long long c) {
    unsigned long long d;
    asm("fma.rn.f32x2 %0, %1, %2, %3;" : "=l"(d) : "l"(a), "l"(b), "l"(c));
    return d;
}

// ---------------- setup kernels ----------------
__global__ void zero_c_kernel() {
    int t = blockIdx.x * blockDim.x + threadIdx.x;
    if (t < S * S * S) g_C2[t] = make_float2(0.0f, 0.0f);
}

__global__ void build_c_kernel(const int* __restrict__ path_indices,
                               const float* __restrict__ path_coeffs) {
    int p = blockIdx.x * blockDim.x + threadIdx.x;
    if (p >= PP) return;
    int i = path_indices[3 * p + 0];   // x segment
    int j = path_indices[3 * p + 1];   // y segment
    int k = path_indices[3 * p + 2];   // out segment
    float cf = path_coeffs[p];
    int idx = (i * S + j) * S + k;
    atomicAdd(&g_C2[idx].x, cf);
    atomicAdd(&g_C2[idx].y, cf);
}

__global__ void zero_out_kernel(float4* __restrict__ out, int n4) {
    int t = blockIdx.x * blockDim.x + threadIdx.x;
    if (t < n4) out[t] = make_float4(0.0f, 0.0f, 0.0f, 0.0f);
}

// ---------------- main contraction ----------------
// Block: 128 threads = 4 edges x 32 lanes. Lane c handles channels (c, c+32)
// packed as one f32x2. Per thread: 4096 FFMA2 + 2048 LDS.128.
constexpr int EDGES_PER_BLOCK = 4;

__global__ __launch_bounds__(128) void seg_poly_kernel(
    const float* __restrict__ x,
    const float* __restrict__ y,
    const int*   __restrict__ idx_in,
    const int*   __restrict__ idx_out,
    float*       __restrict__ out)
{
    __shared__ __align__(16) float2 Cs[S * S * S];   // 32 KB

    // cooperative load of C (vectorized)
    {
        const float4* src = reinterpret_cast<const float4*>(g_C2);
        float4* dst = reinterpret_cast<float4*>(Cs);
        for (int t = threadIdx.x; t < (S * S * S) / 2; t += 128)
            dst[t] = src[t];
    }
    __syncthreads();

    const int le = threadIdx.x >> 5;        // local edge 0..3
    const int c  = threadIdx.x & 31;        // channel (and c+32)
    const int e  = blockIdx.x * EDGES_PER_BLOCK + le;

    const int xrow = idx_in[e];
    const int orow = idx_out[e];

    const float* xp = x + (size_t)xrow * SE + c;
    const float* yp = y + (size_t)e    * SE + c;

    // y segments: registers (indexed only by unrolled j)
    unsigned long long yv[S];
    #pragma unroll
    for (int j = 0; j < S; ++j)
        yv[j] = f32x2_pack(yp[j * EXT], yp[j * EXT + 32]);

    unsigned long long acc[S];
    #pragma unroll
    for (int k = 0; k < S; ++k) acc[k] = 0ULL;

    // outer i-loop kept rolled: body ~6.5 KB SASS, fits I$.
    // 2-deep pipeline on the x pair: the loads for iteration i+1 issue before
    // the FMA block of iteration i, hiding L1 hit latency (~39 cyc).
    float x_lo = xp[0];
    float x_hi = xp[32];
    #pragma unroll 1
    for (int i = 0; i < S; ++i) {
        const unsigned long long a = f32x2_pack(x_lo, x_hi);
        if (i + 1 < S) {
            x_lo = xp[(i + 1) * EXT];
            x_hi = xp[(i + 1) * EXT + 32];
        }
        const float2* crow = Cs + i * (S * S);
        #pragma unroll
        for (int j = 0; j < S; ++j) {
            const unsigned long long p = f32x2_mul(a, yv[j]);
            const ulonglong2* cp = reinterpret_cast<const ulonglong2*>(crow + j * S);
            #pragma unroll
            for (int kk = 0; kk < 8; ++kk) {
                ulonglong2 cc = cp[kk];                       // LDS.128: {C[2kk]x2, C[2kk+1]x2}
                acc[2 * kk]     = f32x2_fma(cc.x, p, acc[2 * kk]);
                acc[2 * kk + 1] = f32x2_fma(cc.y, p, acc[2 * kk + 1]);
            }
        }
    }

    // scatter-add (coalesced 128B RED.ADD.F32 per k per half)
    float* op = out + (size_t)orow * SE + c;
    #pragma unroll
    for (int k = 0; k < S; ++k) {
        float lo, hi;
        f32x2_unpack(acc[k], lo, hi);
        atomicAdd(op + k * EXT,      lo);
        atomicAdd(op + k * EXT + 32, hi);
    }
}

// ---------------- launch ----------------
extern "C" void kernel_launch(void* const* d_in, const int* in_sizes, int n_in,
                              void* d_out, int out_size)
{
    const float* x        = (const float*)d_in[0];
    const float* y        = (const float*)d_in[1];
    const int*   idx_in   = (const int*)d_in[2];
    const int*   idx_out  = (const int*)d_in[3];
    const int*   path_idx = (const int*)d_in[4];
    const float* path_cf  = (const float*)d_in[5];
    float* out = (float*)d_out;

    zero_c_kernel<<<(S * S * S + 255) / 256, 256>>>();
    build_c_kernel<<<(PP + 255) / 256, 256>>>(path_idx, path_cf);

    int n4 = out_size / 4;  // 8M floats -> 2M float4
    zero_out_kernel<<<(n4 + 511) / 512, 512>>>((float4*)d_out, n4);

    seg_poly_kernel<<<EE / EDGES_PER_BLOCK, 128>>>(x, y, idx_in, idx_out, out);
}

// round 4
// speedup vs baseline: 1.4009x; 1.4009x over previous
#include <cuda_runtime.h>
#include <cstdint>

// Problem constants (fixed instance)
constexpr int S   = 16;
constexpr int EXT = 64;
constexpr int SE  = S * EXT;          // 1024
constexpr int NN  = 8192;             // nodes
constexpr int EE  = 16384;            // edges
constexpr int PP  = 2048;             // paths

// Dense coefficient tensor, duplicated into float2 {c,c} so LDS.128 yields two
// ready f32x2 operands. Layout: idx = (i*16 + j)*16 + k   (k contiguous)
__device__ __align__(16) float2 g_C2[S * S * S];

// ---------------- f32x2 packed helpers (sm_103a) ----------------
__device__ __forceinline__ unsigned long long f32x2_pack(float lo, float hi) {
    unsigned long long d;
    asm("mov.b64 %0, {%1, %2};" : "=l"(d) : "f"(lo), "f"(hi));
    return d;
}
__device__ __forceinline__ void f32x2_unpack(unsigned long long v, float& lo, float& hi) {
    asm("mov.b64 {%0, %1}, %2;" : "=f"(lo), "=f"(hi) : "l"(v));
}
__device__ __forceinline__ unsigned long long f32x2_mul(unsigned long long a, unsigned long long b) {
    unsigned long long d;
    asm("mul.rn.f32x2 %0, %1, %2;" : "=l"(d) : "l"(a), "l"(b));
    return d;
}
__device__ __forceinline__ unsigned long long f32x2_fma(unsigned long long a, unsigned long long b,
                                                        unsigned long long c) {
    unsigned long long d;
    asm("fma.rn.f32x2 %0, %1, %2, %3;" : "=l"(d) : "l"(a), "l"(b), "l"(c));
    return d;
}

// ---------------- setup kernels ----------------
__global__ void zero_c_kernel() {
    int t = blockIdx.x * blockDim.x + threadIdx.x;
    if (t < S * S * S) g_C2[t] = make_float2(0.0f, 0.0f);
}

__global__ void build_c_kernel(const int* __restrict__ path_indices,
                               const float* __restrict__ path_coeffs) {
    int p = blockIdx.x * blockDim.x + threadIdx.x;
    if (p >= PP) return;
    int i = path_indices[3 * p + 0];   // x segment
    int j = path_indices[3 * p + 1];   // y segment
    int k = path_indices[3 * p + 2];   // out segment
    float cf = path_coeffs[p];
    int idx = (i * S + j) * S + k;
    atomicAdd(&g_C2[idx].x, cf);
    atomicAdd(&g_C2[idx].y, cf);
}

__global__ void zero_out_kernel(float4* __restrict__ out, int n4) {
    int t = blockIdx.x * blockDim.x + threadIdx.x;
    if (t < n4) out[t] = make_float4(0.0f, 0.0f, 0.0f, 0.0f);
}

// ---------------- main contraction ----------------
// Block: 128 threads = 8 edges x 16 lanes. Lane c in [0,16) handles 4 channels:
// pair A = (c, c+32), pair B = (c+16, c+48), each packed as one f32x2.
// Each LDS.128 of duplicated C feeds 4 FFMA2 (2 k-values x 2 channel-pairs):
// per thread 2048 LDS.128 + 8192 FFMA2 -> LDS traffic halved vs R3, FMA-bound.
constexpr int EDGES_PER_BLOCK = 8;

__global__ __launch_bounds__(128) void seg_poly_kernel(
    const float* __restrict__ x,
    const float* __restrict__ y,
    const int*   __restrict__ idx_in,
    const int*   __restrict__ idx_out,
    float*       __restrict__ out)
{
    __shared__ __align__(16) float2 Cs[S * S * S];   // 32 KB

    // cooperative load of C (vectorized)
    {
        const float4* src = reinterpret_cast<const float4*>(g_C2);
        float4* dst = reinterpret_cast<float4*>(Cs);
        for (int t = threadIdx.x; t < (S * S * S) / 2; t += 128)
            dst[t] = src[t];
    }
    __syncthreads();

    const int le = threadIdx.x >> 4;        // local edge 0..7
    const int c  = threadIdx.x & 15;        // base channel
    const int e  = blockIdx.x * EDGES_PER_BLOCK + le;

    const int xrow = idx_in[e];
    const int orow = idx_out[e];

    const float* xp = x + (size_t)xrow * SE + c;
    const float* yp = y + (size_t)e    * SE + c;

    // y segments: registers (indexed only by unrolled j)
    unsigned long long yvA[S];
    unsigned long long yvB[S];
    #pragma unroll
    for (int j = 0; j < S; ++j) {
        yvA[j] = f32x2_pack(yp[j * EXT     ], yp[j * EXT + 32]);
        yvB[j] = f32x2_pack(yp[j * EXT + 16], yp[j * EXT + 48]);
    }

    unsigned long long accA[S];
    unsigned long long accB[S];
    #pragma unroll
    for (int k = 0; k < S; ++k) { accA[k] = 0ULL; accB[k] = 0ULL; }

    // outer i-loop rolled; 2-deep pipeline on the 4 x-values hides L1 latency.
    float xa0 = xp[0],  xa1 = xp[32];
    float xb0 = xp[16], xb1 = xp[48];
    #pragma unroll 1
    for (int i = 0; i < S; ++i) {
        const unsigned long long aA = f32x2_pack(xa0, xa1);
        const unsigned long long aB = f32x2_pack(xb0, xb1);
        if (i + 1 < S) {
            xa0 = xp[(i + 1) * EXT     ];
            xa1 = xp[(i + 1) * EXT + 32];
            xb0 = xp[(i + 1) * EXT + 16];
            xb1 = xp[(i + 1) * EXT + 48];
        }
        const float2* crow = Cs + i * (S * S);
        #pragma unroll
        for (int j = 0; j < S; ++j) {
            const unsigned long long pA = f32x2_mul(aA, yvA[j]);
            const unsigned long long pB = f32x2_mul(aB, yvB[j]);
            const ulonglong2* cp = reinterpret_cast<const ulonglong2*>(crow + j * S);
            #pragma unroll
            for (int kk = 0; kk < 8; ++kk) {
                ulonglong2 cc = cp[kk];               // LDS.128: {C[2kk]x2, C[2kk+1]x2}
                accA[2 * kk]     = f32x2_fma(cc.x, pA, accA[2 * kk]);
                accB[2 * kk]     = f32x2_fma(cc.x, pB, accB[2 * kk]);
                accA[2 * kk + 1] = f32x2_fma(cc.y, pA, accA[2 * kk + 1]);
                accB[2 * kk + 1] = f32x2_fma(cc.y, pB, accB[2 * kk + 1]);
            }
        }
    }

    // scatter-add (coalesced 64B RED.ADD.F32 segments per k per quarter)
    float* op = out + (size_t)orow * SE + c;
    #pragma unroll
    for (int k = 0; k < S; ++k) {
        float a0, a1, b0, b1;
        f32x2_unpack(accA[k], a0, a1);
        f32x2_unpack(accB[k], b0, b1);
        atomicAdd(op + k * EXT,      a0);
        atomicAdd(op + k * EXT + 16, b0);
        atomicAdd(op + k * EXT + 32, a1);
        atomicAdd(op + k * EXT + 48, b1);
    }
}

// ---------------- launch ----------------
extern "C" void kernel_launch(void* const* d_in, const int* in_sizes, int n_in,
                              void* d_out, int out_size)
{
    const float* x        = (const float*)d_in[0];
    const float* y        = (const float*)d_in[1];
    const int*   idx_in   = (const int*)d_in[2];
    const int*   idx_out  = (const int*)d_in[3];
    const int*   path_idx = (const int*)d_in[4];
    const float* path_cf  = (const float*)d_in[5];
    float* out = (float*)d_out;

    zero_c_kernel<<<(S * S * S + 255) / 256, 256>>>();
    build_c_kernel<<<(PP + 255) / 256, 256>>>(path_idx, path_cf);

    int n4 = out_size / 4;  // 8M floats -> 2M float4
    zero_out_kernel<<<(n4 + 511) / 512, 512>>>((float4*)d_out, n4);

    seg_poly_kernel<<<EE / EDGES_PER_BLOCK, 128>>>(x, y, idx_in, idx_out, out);
}